// round 5
// baseline (speedup 1.0000x reference)
#include <cuda_runtime.h>
#include <math.h>

#define L 64
static const int NMAX = 100352;
static const int EMAX = 1605632;

__device__ __align__(16) float g_deg[NMAX];
__device__ __align__(16) float g_dinv[NMAX];
__device__ __align__(16) float g_rcp[NMAX];
__device__ int   g_cnti[NMAX];
__device__ int   g_offs[NMAX];
__device__ int   g_cursor[NMAX];
__device__ int   g_bsums[1024];
__device__ __align__(16) uint2 g_csr[EMAX];   // .x = row idx, .y = norm bits
__device__ __align__(16) float g_h [(size_t)NMAX * L];
__device__ __align__(16) float g_t0[(size_t)NMAX * L];
__device__ __align__(16) float g_t1[(size_t)NMAX * L];
__device__ int   g_is64;

// ---- packed f32x2 helpers (sm_100+) ----------------------------------------
__device__ __forceinline__ unsigned long long dup2(float x) {
    unsigned long long d;
    asm("mov.b64 %0, {%1, %1};" : "=l"(d) : "f"(x));
    return d;
}
__device__ __forceinline__ void ffma2(unsigned long long& d,
                                      unsigned long long a, unsigned long long b) {
    asm("fma.rn.f32x2 %0, %1, %2, %0;" : "+l"(d) : "l"(a), "l"(b));
}
__device__ __forceinline__ float2 unpack2(unsigned long long d) {
    float2 f;
    asm("mov.b64 {%0, %1}, %2;" : "=f"(f.x), "=f"(f.y) : "l"(d));
    return f;
}

__global__ void k_detect(const unsigned int* er) {
    if (blockIdx.x == 0 && threadIdx.x == 0) {
        int ok = 1;
        #pragma unroll
        for (int i = 0; i < 64; i++)
            if (er[2 * i + 1] != 0u) ok = 0;
        g_is64 = ok;
    }
}

__device__ __forceinline__ int ld_idx(const void* p, int e, int is64) {
    if (is64) return (int)((const long long*)p)[e];
    return ((const int*)p)[e];
}

__global__ void k_zero2(float* pf, int* pi, int n) {
    int i = blockIdx.x * blockDim.x + threadIdx.x;
    if (i < n) { pf[i] = 0.0f; pi[i] = 0; }
}

__global__ void k_deg_cnt(const float* __restrict__ attr, const void* colp, int E) {
    int is64 = g_is64;
    int e = blockIdx.x * blockDim.x + threadIdx.x;
    if (e < E) {
        int c = ld_idx(colp, e, is64);
        atomicAdd(&g_deg[c], attr[e]);
        atomicAdd(&g_cnti[c], 1);
    }
}

__global__ void k_dinv(int N) {
    int n = blockIdx.x * blockDim.x + threadIdx.x;
    if (n < N) {
        float d = g_deg[n];
        g_dinv[n] = (d > 0.0f) ? rsqrtf(fmaxf(d, 1e-30f)) : 0.0f;
        g_rcp[n] = 1.0f / fmaxf((float)g_cnti[n], 1.0f);
    }
}

// ---------------- prefix scan over counts -----------------------------------
__global__ void k_scan1(int N) {
    __shared__ int wsum[8];
    int t = threadIdx.x;
    int base = blockIdx.x * 1024 + t * 4;
    int v0 = 0, v1 = 0, v2 = 0, v3 = 0;
    if (base + 0 < N) v0 = g_cnti[base + 0];
    if (base + 1 < N) v1 = g_cnti[base + 1];
    if (base + 2 < N) v2 = g_cnti[base + 2];
    if (base + 3 < N) v3 = g_cnti[base + 3];
    int s = v0 + v1 + v2 + v3;
    int lane = t & 31, warp = t >> 5;
    int x = s;
    #pragma unroll
    for (int o = 1; o < 32; o <<= 1) {
        int y = __shfl_up_sync(0xffffffffu, x, o);
        if (lane >= o) x += y;
    }
    if (lane == 31) wsum[warp] = x;
    __syncthreads();
    if (warp == 0 && lane < 8) {
        int w = wsum[lane];
        #pragma unroll
        for (int o = 1; o < 8; o <<= 1) {
            int y = __shfl_up_sync(0x000000ffu, w, o);
            if (lane >= o) w += y;
        }
        wsum[lane] = w;
    }
    __syncthreads();
    int excl = x - s + (warp > 0 ? wsum[warp - 1] : 0);
    int r = excl;
    r += v0; if (base + 0 < N) g_offs[base + 0] = r;
    r += v1; if (base + 1 < N) g_offs[base + 1] = r;
    r += v2; if (base + 2 < N) g_offs[base + 2] = r;
    r += v3; if (base + 3 < N) g_offs[base + 3] = r;
    if (t == 255) g_bsums[blockIdx.x] = excl + s;
}

__global__ void k_scan2(int nb) {
    if (threadIdx.x == 0 && blockIdx.x == 0) {
        int run = 0;
        for (int i = 0; i < nb; i++) { int t = g_bsums[i]; g_bsums[i] = run; run += t; }
    }
}

__global__ void k_scan3(int N) {
    int i = blockIdx.x * blockDim.x + threadIdx.x;
    if (i < N) {
        int excl = g_offs[i] + g_bsums[i >> 10] - g_cnti[i];
        g_offs[i] = excl;
        g_cursor[i] = excl;
    }
}

// CSR fill with inline GCN norm: rec.y = dinv[r]*attr*dinv[c]
__global__ void k_csr_fill(const float* __restrict__ attr, const void* rowp,
                           const void* colp, int E) {
    int is64 = g_is64;
    int e = blockIdx.x * blockDim.x + threadIdx.x;
    if (e < E) {
        int r = ld_idx(rowp, e, is64);
        int c = ld_idx(colp, e, is64);
        int p = atomicAdd(&g_cursor[c], 1);
        uint2 rec;
        rec.x = (unsigned int)r;
        rec.y = __float_as_uint(g_dinv[r] * attr[e] * g_dinv[c]);
        g_csr[p] = rec;
    }
}

__global__ void k_enc(const float* __restrict__ x, const float* __restrict__ w,
                      const float* __restrict__ b, int N) {
    int i = blockIdx.x * blockDim.x + threadIdx.x;
    if (i < N * L) {
        int n = i >> 6, f = i & 63;
        g_h[i] = x[n] * w[f] + b[f];
    }
}

// ---- aggregation: agg[n] = rcp[n] * sum_e norm_e * hin[row_e]  (warp/node) --
__global__ void __launch_bounds__(256)
k_agg(const float* __restrict__ hin, float* __restrict__ aggo, int N) {
    int warp = threadIdx.x >> 5, lane = threadIdx.x & 31;
    int n = blockIdx.x * 8 + warp;
    if (n >= N) return;
    int lane2 = lane * 2;
    int st = g_offs[n];
    int en = st + g_cnti[n];
    unsigned long long a0 = 0ull, a1 = 0ull;
    int k = st;
    #pragma unroll 1
    for (; k + 4 <= en; k += 4) {
        uint2 e0 = g_csr[k + 0];
        uint2 e1 = g_csr[k + 1];
        uint2 e2 = g_csr[k + 2];
        uint2 e3 = g_csr[k + 3];
        unsigned long long v0 = *(const unsigned long long*)(hin + ((size_t)e0.x << 6) + lane2);
        unsigned long long v1 = *(const unsigned long long*)(hin + ((size_t)e1.x << 6) + lane2);
        unsigned long long v2 = *(const unsigned long long*)(hin + ((size_t)e2.x << 6) + lane2);
        unsigned long long v3 = *(const unsigned long long*)(hin + ((size_t)e3.x << 6) + lane2);
        ffma2(a0, v0, dup2(__uint_as_float(e0.y)));
        ffma2(a1, v1, dup2(__uint_as_float(e1.y)));
        ffma2(a0, v2, dup2(__uint_as_float(e2.y)));
        ffma2(a1, v3, dup2(__uint_as_float(e3.y)));
    }
    #pragma unroll 1
    for (; k < en; k++) {
        uint2 rec = g_csr[k];
        unsigned long long v = *(const unsigned long long*)(hin + ((size_t)rec.x << 6) + lane2);
        ffma2(a0, v, dup2(__uint_as_float(rec.y)));
    }
    float rcp = g_rcp[n];
    float2 s0 = unpack2(a0), s1 = unpack2(a1);
    float2 o;
    o.x = (s0.x + s1.x) * rcp;
    o.y = (s0.y + s1.y) * rcp;
    *(float2*)(aggo + ((size_t)n << 6) + lane2) = o;
}

// ---- GEMM: 128 rows/block, 8x8 per-thread tile, packed f32x2 FMA -----------
// Stores/loads unconditionally: grid*128 <= NMAX, buffers are NMAX rows.
template<bool RELU>
__global__ void __launch_bounds__(128)
k_gemm8(const float* __restrict__ X, const float* __restrict__ W,
        const float* __restrict__ bias, float* __restrict__ Y) {
    __shared__ float Ws[64][64];
    __shared__ float Xs[128][65];
    int tid = threadIdx.x;
    const float4* W4 = (const float4*)W;
    #pragma unroll
    for (int i = 0; i < 8; i++) {
        int idx = tid + i * 128;
        *(float4*)&Ws[idx >> 4][(idx & 15) * 4] = W4[idx];
    }
    size_t base = (size_t)blockIdx.x * (128 * 64);
    const float4* X4 = (const float4*)(X + base);
    #pragma unroll
    for (int i = 0; i < 16; i++) {
        int idx = tid + i * 128;
        float4 v = X4[idx];
        int row = idx >> 4, k0 = (idx & 15) * 4;
        Xs[row][k0 + 0] = v.x;
        Xs[row][k0 + 1] = v.y;
        Xs[row][k0 + 2] = v.z;
        Xs[row][k0 + 3] = v.w;
    }
    __syncthreads();
    int tr = (tid >> 3) * 8;   // 16 groups of 8 rows
    int tc = (tid & 7) * 8;    // 8 groups of 8 cols
    unsigned long long acc[8][4];
    #pragma unroll
    for (int r = 0; r < 8; r++)
        #pragma unroll
        for (int p = 0; p < 4; p++) acc[r][p] = 0ull;
    #pragma unroll 2
    for (int k = 0; k < 64; k++) {
        unsigned long long w0 = *(const unsigned long long*)&Ws[k][tc + 0];
        unsigned long long w1 = *(const unsigned long long*)&Ws[k][tc + 2];
        unsigned long long w2 = *(const unsigned long long*)&Ws[k][tc + 4];
        unsigned long long w3 = *(const unsigned long long*)&Ws[k][tc + 6];
        #pragma unroll
        for (int r = 0; r < 8; r++) {
            unsigned long long xd = dup2(Xs[tr + r][k]);
            ffma2(acc[r][0], xd, w0);
            ffma2(acc[r][1], xd, w1);
            ffma2(acc[r][2], xd, w2);
            ffma2(acc[r][3], xd, w3);
        }
    }
    float2 b0 = make_float2(0.f, 0.f), b1 = b0, b2 = b0, b3 = b0;
    if (bias) {
        b0 = *(const float2*)(bias + tc + 0);
        b1 = *(const float2*)(bias + tc + 2);
        b2 = *(const float2*)(bias + tc + 4);
        b3 = *(const float2*)(bias + tc + 6);
    }
    #pragma unroll
    for (int r = 0; r < 8; r++) {
        float2 c0 = unpack2(acc[r][0]);
        float2 c1 = unpack2(acc[r][1]);
        float2 c2 = unpack2(acc[r][2]);
        float2 c3 = unpack2(acc[r][3]);
        float4 oA, oB;
        oA.x = c0.x + b0.x; oA.y = c0.y + b0.y;
        oA.z = c1.x + b1.x; oA.w = c1.y + b1.y;
        oB.x = c2.x + b2.x; oB.y = c2.y + b2.y;
        oB.z = c3.x + b3.x; oB.w = c3.y + b3.y;
        if (RELU) {
            oA.x = fmaxf(oA.x, 0.f); oA.y = fmaxf(oA.y, 0.f);
            oA.z = fmaxf(oA.z, 0.f); oA.w = fmaxf(oA.w, 0.f);
            oB.x = fmaxf(oB.x, 0.f); oB.y = fmaxf(oB.y, 0.f);
            oB.z = fmaxf(oB.z, 0.f); oB.w = fmaxf(oB.w, 0.f);
        }
        float* y = Y + base + (size_t)(tr + r) * 64 + tc;
        *(float4*)(y + 0) = oA;
        *(float4*)(y + 4) = oB;
    }
}

// ---- decoder: out[e] = relu(A[r]+B[c]+b1).w2 + b2 ; softplus on diag -------
#define DEC_EPW 8
__global__ void __launch_bounds__(256)
k_dec(const void* rowp, const void* colp,
      const float* __restrict__ b1, const float* __restrict__ w2,
      const float* __restrict__ b2, float* __restrict__ out, int E) {
    int is64 = g_is64;
    int gw   = (blockIdx.x * blockDim.x + threadIdx.x) >> 5;
    int lane = threadIdx.x & 31;
    int lane2 = lane * 2;
    float2 bias = *(const float2*)(b1 + lane2);
    float2 w    = *(const float2*)(w2 + lane2);
    float  bout = b2[0];
    int e0 = gw * DEC_EPW;
    if (e0 >= E) return;
    int m = E - e0; if (m > DEC_EPW) m = DEC_EPW;

    int   rr[DEC_EPW], cc[DEC_EPW];
    float s[DEC_EPW];
    #pragma unroll
    for (int j = 0; j < DEC_EPW; j++) {
        if (j < m) {
            int r = ld_idx(rowp, e0 + j, is64);
            int c = ld_idx(colp, e0 + j, is64);
            rr[j] = r; cc[j] = c;
            float2 a  = *(const float2*)(g_t0 + ((size_t)r << 6) + lane2);
            float2 bb = *(const float2*)(g_t1 + ((size_t)c << 6) + lane2);
            s[j] = fmaxf(a.x + bb.x + bias.x, 0.f) * w.x
                 + fmaxf(a.y + bb.y + bias.y, 0.f) * w.y;
        }
    }
    #pragma unroll
    for (int j = 0; j < DEC_EPW; j++) {
        if (j < m) {
            float v = s[j];
            #pragma unroll
            for (int off = 16; off; off >>= 1)
                v += __shfl_down_sync(0xffffffffu, v, off);
            if (lane == 0) {
                float val = v + bout;
                if (rr[j] == cc[j])
                    val = fmaxf(val, 0.f) + log1pf(expf(-fabsf(val)));
                out[e0 + j] = val;
            }
        }
    }
}

extern "C" void kernel_launch(void* const* d_in, const int* in_sizes, int n_in,
                              void* d_out, int out_size) {
    const float* x        = (const float*)d_in[0];
    const float* eattr    = (const float*)d_in[1];
    const float* w_enc    = (const float*)d_in[2];
    const float* b_enc    = (const float*)d_in[3];
    const float* conv1_w  = (const float*)d_in[4];
    const float* conv1_b  = (const float*)d_in[5];
    const float* conv2_w  = (const float*)d_in[6];
    const float* conv2_b  = (const float*)d_in[7];
    const float* dec_w1   = (const float*)d_in[8];
    const float* dec_b1   = (const float*)d_in[9];
    const float* dec_w2   = (const float*)d_in[10];
    const float* dec_b2   = (const float*)d_in[11];
    const void*  rowp     = d_in[12];
    const void*  colp     = d_in[13];
    float* out = (float*)d_out;

    const int N = in_sizes[0];
    const int E = in_sizes[1];

    float *p_deg, *p_h, *p_t0, *p_t1;
    int *p_cnti;
    cudaGetSymbolAddress((void**)&p_deg, g_deg);
    cudaGetSymbolAddress((void**)&p_h,   g_h);
    cudaGetSymbolAddress((void**)&p_t0,  g_t0);
    cudaGetSymbolAddress((void**)&p_t1,  g_t1);
    cudaGetSymbolAddress((void**)&p_cnti, g_cnti);

    const int TB = 256;
    int eb  = (E + TB - 1) / TB;
    int nb  = (N + TB - 1) / TB;
    int nfb = (N * L + TB - 1) / TB;
    int gb2 = (N + 127) / 128;
    int ab  = (N + 7) / 8;
    int nsb = (N + 1023) / 1024;
    int db  = (int)(((long long)E + DEC_EPW * 8 - 1) / (DEC_EPW * 8));

    k_detect<<<1, 64>>>((const unsigned int*)rowp);

    k_zero2<<<nb, TB>>>(p_deg, p_cnti, N);
    k_deg_cnt<<<eb, TB>>>(eattr, colp, E);
    k_dinv<<<nb, TB>>>(N);

    k_scan1<<<nsb, 256>>>(N);
    k_scan2<<<1, 32>>>(nsb);
    k_scan3<<<nb, TB>>>(N);
    k_csr_fill<<<eb, TB>>>(eattr, rowp, colp, E);

    k_enc<<<nfb, TB>>>(x, w_enc, b_enc, N);

    // 6 GCN layers: agg (cur -> t1), gemm+bias+relu (t1 -> nxt)
    float* cur = p_h;
    float* nxt = p_t0;
    for (int i = 0; i < 3; i++) {
        k_agg<<<ab, TB>>>(cur, p_t1, N);
        k_gemm8<true><<<gb2, 128>>>(p_t1, conv1_w + (size_t)i * 4096,
                                    conv1_b + (size_t)i * 64, nxt);
        { float* t = cur; cur = nxt; nxt = t; }
        k_agg<<<ab, TB>>>(cur, p_t1, N);
        k_gemm8<true><<<gb2, 128>>>(p_t1, conv2_w + (size_t)i * 4096,
                                    conv2_b + (size_t)i * 64, nxt);
        { float* t = cur; cur = nxt; nxt = t; }
    }
    // cur == p_h after 6 layers

    k_gemm8<false><<<gb2, 128>>>(cur, dec_w1,        (const float*)0, p_t0);
    k_gemm8<false><<<gb2, 128>>>(cur, dec_w1 + 4096, (const float*)0, p_t1);
    k_dec<<<db, TB>>>(rowp, colp, dec_b1, dec_w2, dec_b2, out, E);
}